// round 2
// baseline (speedup 1.0000x reference)
#include <cuda_runtime.h>
#include <math.h>
#include <stdint.h>

#define B_ 256
#define D_ 512
#define C_ 100000
#define SCALEF 64.0f
#define MARGINF 0.4f

// ---------------- device scratch (static, no runtime allocation) ----------------
__device__ __align__(16) float g_At[D_ * B_];          // normalized A, transposed [k][m]
__device__ __align__(16) float g_inv[C_ + 128];        // 1/colnorm
__device__ __align__(16) float g_cos[(size_t)B_ * C_]; // clipped cosine matrix, 102.4MB
__device__ float   g_tgt[B_];
__device__ int     g_topk_sum;
__device__ unsigned g_h1[4096];
__device__ unsigned g_h2[4096];
__device__ unsigned g_h3[256];
__device__ unsigned g_sel_prefix;
__device__ int     g_sel_rank;
__device__ float   g_neg_th;
__device__ float   g_loss_sum;
__device__ int     g_acc_sum;

// monotone float <-> u32 key (ascending value -> ascending key)
__device__ __forceinline__ unsigned fkey(float v) {
    unsigned u = __float_as_uint(v);
    return (u & 0x80000000u) ? ~u : (u | 0x80000000u);
}
__device__ __forceinline__ float funkey(unsigned k) {
    unsigned u = (k & 0x80000000u) ? (k & 0x7fffffffu) : ~k;
    return __uint_as_float(u);
}

// ---------------- init ----------------
__global__ void k_init() {
    int t = threadIdx.x;
    for (int i = t; i < 4096; i += blockDim.x) { g_h1[i] = 0u; g_h2[i] = 0u; }
    if (t < 256) g_h3[t] = 0u;
    if (t == 0) { g_topk_sum = 0; g_loss_sum = 0.f; g_acc_sum = 0; }
}

// ---------------- normalize embeddings, write transposed [k][m] ----------------
__global__ void k_normA(const float* __restrict__ emb) {
    int r = blockIdx.x, t = threadIdx.x; // 256 threads
    float v0 = emb[r * D_ + t];
    float v1 = emb[r * D_ + 256 + t];
    __shared__ float red[256];
    red[t] = v0 * v0 + v1 * v1;
    __syncthreads();
    for (int o = 128; o > 0; o >>= 1) {
        if (t < o) red[t] += red[t + o];
        __syncthreads();
    }
    float inv = 1.0f / sqrtf(red[0]);
    g_At[t * B_ + r] = v0 * inv;
    g_At[(256 + t) * B_ + r] = v1 * inv;
}

// ---------------- column norms of kernel ----------------
__global__ void k_colnorm(const float* __restrict__ K) {
    int c = blockIdx.x * blockDim.x + threadIdx.x;
    if (c >= C_) return;
    float s = 0.f;
#pragma unroll 8
    for (int k = 0; k < D_; k++) {
        float v = K[(size_t)k * C_ + c];
        s += v * v;
    }
    g_inv[c] = 1.0f / sqrtf(s);
}

// ---------------- GEMM: cos = clip( (A_n @ K) * inv_col, -1, 1 ) ----------------
#define BM 128
#define BN 128
#define BK 16

__global__ void __launch_bounds__(256, 2) k_gemm(const float* __restrict__ Kmat) {
    __shared__ __align__(16) float As[2][BK][BM];
    __shared__ __align__(16) float Bs[2][BK][BN];
    const int n0 = blockIdx.x * BN;
    const int m0 = blockIdx.y * BM;
    const int tid = threadIdx.x;
    const int tx = tid & 15, ty = tid >> 4;
    const int lk = tid >> 5;          // 0..7
    const int lm = (tid & 31) << 2;   // 0..124

    float acc[8][8];
#pragma unroll
    for (int i = 0; i < 8; i++)
#pragma unroll
        for (int j = 0; j < 8; j++) acc[i][j] = 0.f;

    const int colg = n0 + lm;
    const bool colok = (colg < C_);

    float4 ra0, ra1, rb0, rb1;
    {
        const float* pa = g_At + lk * B_ + m0 + lm;
        ra0 = *(const float4*)pa;
        ra1 = *(const float4*)(pa + 8 * B_);
        if (colok) {
            const float* pb = Kmat + (size_t)lk * C_ + colg;
            rb0 = *(const float4*)pb;
            rb1 = *(const float4*)(pb + (size_t)8 * C_);
        } else {
            rb0 = make_float4(0.f, 0.f, 0.f, 0.f);
            rb1 = rb0;
        }
    }
    *(float4*)&As[0][lk][lm] = ra0; *(float4*)&As[0][lk + 8][lm] = ra1;
    *(float4*)&Bs[0][lk][lm] = rb0; *(float4*)&Bs[0][lk + 8][lm] = rb1;
    __syncthreads();

    int buf = 0;
    const int NKC = D_ / BK; // 32
    for (int kc = 0; kc < NKC; kc++) {
        if (kc + 1 < NKC) {
            const float* pa = g_At + ((kc + 1) * BK + lk) * B_ + m0 + lm;
            ra0 = *(const float4*)pa;
            ra1 = *(const float4*)(pa + 8 * B_);
            if (colok) {
                const float* pb = Kmat + (size_t)((kc + 1) * BK + lk) * C_ + colg;
                rb0 = *(const float4*)pb;
                rb1 = *(const float4*)(pb + (size_t)8 * C_);
            } else {
                rb0 = make_float4(0.f, 0.f, 0.f, 0.f);
                rb1 = rb0;
            }
        }
#pragma unroll
        for (int kk = 0; kk < BK; kk++) {
            float4 av0 = *(const float4*)&As[buf][kk][ty * 4];
            float4 av1 = *(const float4*)&As[buf][kk][64 + ty * 4];
            float4 bv0 = *(const float4*)&Bs[buf][kk][tx * 4];
            float4 bv1 = *(const float4*)&Bs[buf][kk][64 + tx * 4];
            float a[8] = {av0.x, av0.y, av0.z, av0.w, av1.x, av1.y, av1.z, av1.w};
            float b[8] = {bv0.x, bv0.y, bv0.z, bv0.w, bv1.x, bv1.y, bv1.z, bv1.w};
#pragma unroll
            for (int i = 0; i < 8; i++)
#pragma unroll
                for (int j = 0; j < 8; j++)
                    acc[i][j] = fmaf(a[i], b[j], acc[i][j]);
        }
        if (kc + 1 < NKC) {
            int nb = buf ^ 1;
            *(float4*)&As[nb][lk][lm] = ra0; *(float4*)&As[nb][lk + 8][lm] = ra1;
            *(float4*)&Bs[nb][lk][lm] = rb0; *(float4*)&Bs[nb][lk + 8][lm] = rb1;
            __syncthreads();
            buf = nb;
        }
    }

    // epilogue: apply inv col norm, clip, store
    float inv[8];
#pragma unroll
    for (int h = 0; h < 2; h++)
#pragma unroll
        for (int j = 0; j < 4; j++) {
            int c = n0 + h * 64 + tx * 4 + j;
            inv[h * 4 + j] = (c < C_) ? g_inv[c] : 0.f;
        }
#pragma unroll
    for (int gi = 0; gi < 2; gi++) {
#pragma unroll
        for (int i = 0; i < 4; i++) {
            int m = m0 + gi * 64 + ty * 4 + i;
#pragma unroll
            for (int h = 0; h < 2; h++) {
                int c = n0 + h * 64 + tx * 4;
                if (c < C_) {
                    float4 o;
                    o.x = fminf(fmaxf(acc[gi * 4 + i][h * 4 + 0] * inv[h * 4 + 0], -1.f), 1.f);
                    o.y = fminf(fmaxf(acc[gi * 4 + i][h * 4 + 1] * inv[h * 4 + 1], -1.f), 1.f);
                    o.z = fminf(fmaxf(acc[gi * 4 + i][h * 4 + 2] * inv[h * 4 + 2], -1.f), 1.f);
                    o.w = fminf(fmaxf(acc[gi * 4 + i][h * 4 + 3] * inv[h * 4 + 3], -1.f), 1.f);
                    *(float4*)&g_cos[(size_t)m * C_ + c] = o;
                }
            }
        }
    }
}

// ---------------- gather target cosines ----------------
__global__ void k_tgt(const int* __restrict__ label) {
    int t = threadIdx.x;
    g_tgt[t] = g_cos[(size_t)t * C_ + label[t]];
}

// ---------------- stats: topk count, argmax(acc), level-1 histogram ----------------
__global__ void k_stats(const int* __restrict__ label) {
    const int row = blockIdx.x;
    const int t = threadIdx.x; // 512 threads
    const float tgt = g_tgt[row];
    const int lab = label[row];

    __shared__ unsigned sh[4096];
    for (int i = t; i < 4096; i += 512) sh[i] = 0u;
    __syncthreads();

    const float4* rp = (const float4*)(g_cos + (size_t)row * C_);
    const int NV = C_ / 4;                 // 25000
    const int NPAD = ((NV + 511) / 512) * 512; // 25088 -> uniform trip count

    int cnt = 0;
    float mx = -2.f;
    int mi = 0;

    for (int q = t; q < NPAD; q += 512) {
        bool ok = (q < NV);
        float4 v = ok ? rp[q] : make_float4(0.f, 0.f, 0.f, 0.f);
#pragma unroll
        for (int e = 0; e < 4; e++) {
            unsigned bin = 0;
            if (ok) {
                float c = (&v.x)[e];
                int j = q * 4 + e;
                if (c > mx) { mx = c; mi = j; }
                float tmp = (j == lab) ? c - 2.f : c;
                bool tk = tmp > tgt;
                cnt += tk ? 1 : 0;
                float flat = tk ? tmp - 2.f : tmp;
                bin = fkey(flat) >> 20;
            }
            unsigned act = __ballot_sync(0xffffffffu, ok);
            if (ok) {
                unsigned mmask = __match_any_sync(act, bin);
                int leader = __ffs(mmask) - 1;
                if ((t & 31) == leader) atomicAdd(&sh[bin], (unsigned)__popc(mmask));
            }
        }
    }

    __shared__ float smx[512];
    __shared__ int smi[512];
    __shared__ int scnt[512];
    smx[t] = mx; smi[t] = mi; scnt[t] = cnt;
    __syncthreads();
    for (int o = 256; o > 0; o >>= 1) {
        if (t < o) {
            scnt[t] += scnt[t + o];
            float v2 = smx[t + o]; int i2 = smi[t + o];
            if (v2 > smx[t] || (v2 == smx[t] && i2 < smi[t])) { smx[t] = v2; smi[t] = i2; }
        }
        __syncthreads();
    }
    if (t == 0) {
        atomicAdd(&g_topk_sum, scnt[0]);
        if (smi[0] == lab) atomicAdd(&g_acc_sum, 1);
    }
    for (int i = t; i < 4096; i += 512)
        if (sh[i]) atomicAdd(&g_h1[i], sh[i]);
}

// ---------------- generic descending scan over a histogram level ----------------
__global__ void k_scan(int level) {
    const int t = threadIdx.x; // 512 threads
    const unsigned* hist = (level == 1) ? g_h1 : (level == 2) ? g_h2 : g_h3;
    const int nbins = (level == 3) ? 256 : 4096;

    int r;
    if (level == 1) {
        int ts = g_topk_sum;
        float far = (float)(1.0 / 99999.0);
        float fr = ceilf(far * (float)(25599744 - ts));
        int fri = (int)fr;
        if (fri < 1) fri = 1;
        r = fri;
    } else {
        r = g_sel_rank;
    }

    const int chunk = (nbins + 511) / 512;
    __shared__ unsigned csum[512];
    unsigned s = 0;
    for (int i = 0; i < chunk; i++) {
        int b = nbins - 1 - (t * chunk + i);
        if (b >= 0) s += hist[b];
    }
    csum[t] = s;
    __syncthreads();
    for (int o = 1; o < 512; o <<= 1) {
        unsigned v = (t >= o) ? csum[t - o] : 0u;
        __syncthreads();
        csum[t] += v;
        __syncthreads();
    }
    unsigned mycum = csum[t];
    unsigned before = (t == 0) ? 0u : csum[t - 1];
    if (mycum >= (unsigned)r && before < (unsigned)r) {
        unsigned acc2 = before;
        for (int i = 0; i < chunk; i++) {
            int b = nbins - 1 - (t * chunk + i);
            if (b < 0) break;
            unsigned hb = hist[b];
            acc2 += hb;
            if (acc2 >= (unsigned)r) {
                int rrem = r - (int)(acc2 - hb);
                if (level == 1) {
                    g_sel_prefix = (unsigned)b;
                    g_sel_rank = rrem;
                } else if (level == 2) {
                    g_sel_prefix = (g_sel_prefix << 12) | (unsigned)b;
                    g_sel_rank = rrem;
                } else {
                    unsigned key = (g_sel_prefix << 8) | (unsigned)b;
                    g_neg_th = funkey(key);
                }
                break;
            }
        }
    }
}

// ---------------- level-2 / level-3 restricted histograms ----------------
__global__ void k_hist2(const int* __restrict__ label) {
    const int row = blockIdx.x, t = threadIdx.x;
    const float tgt = g_tgt[row];
    const int lab = label[row];
    const unsigned pref = g_sel_prefix;
    const float4* rp = (const float4*)(g_cos + (size_t)row * C_);
    for (int q = t; q < C_ / 4; q += 512) {
        float4 v = rp[q];
#pragma unroll
        for (int e = 0; e < 4; e++) {
            float c = (&v.x)[e];
            int j = q * 4 + e;
            float tmp = (j == lab) ? c - 2.f : c;
            float flat = (tmp > tgt) ? tmp - 2.f : tmp;
            unsigned key = fkey(flat);
            if ((key >> 20) == pref) atomicAdd(&g_h2[(key >> 8) & 0xFFFu], 1u);
        }
    }
}

__global__ void k_hist3(const int* __restrict__ label) {
    const int row = blockIdx.x, t = threadIdx.x;
    const float tgt = g_tgt[row];
    const int lab = label[row];
    const unsigned pref = g_sel_prefix; // 24-bit prefix
    const float4* rp = (const float4*)(g_cos + (size_t)row * C_);
    for (int q = t; q < C_ / 4; q += 512) {
        float4 v = rp[q];
#pragma unroll
        for (int e = 0; e < 4; e++) {
            float c = (&v.x)[e];
            int j = q * 4 + e;
            float tmp = (j == lab) ? c - 2.f : c;
            float flat = (tmp > tgt) ? tmp - 2.f : tmp;
            unsigned key = fkey(flat);
            if ((key >> 8) == pref) atomicAdd(&g_h3[key & 0xFFu], 1u);
        }
    }
}

// ---------------- per-row: neg mean, margin target, online softmax, loss ----------------
__global__ void k_row(const int* __restrict__ label) {
    const int row = blockIdx.x, t = threadIdx.x; // 512 threads
    const float tgt = g_tgt[row];
    const int lab = label[row];
    const float nth = g_neg_th;
    const float4* rp = (const float4*)(g_cos + (size_t)row * C_);

    float ssum = 0.f;
    int ncnt = 0;
    for (int q = t; q < C_ / 4; q += 512) {
        float4 v = rp[q];
#pragma unroll
        for (int e = 0; e < 4; e++) {
            float c = (&v.x)[e];
            int j = q * 4 + e;
            float tmp = (j == lab) ? c - 2.f : c;
            bool cond = (tmp <= tgt) && (tmp > nth);
            if (cond) {
                float sq = tmp * tmp;
                ssum += sq;
                if (sq > 0.f) ncnt++;
            }
        }
    }

    __shared__ float sf[512];
    __shared__ int si[512];
    sf[t] = ssum; si[t] = ncnt;
    __syncthreads();
    for (int o = 256; o > 0; o >>= 1) {
        if (t < o) { sf[t] += sf[t + o]; si[t] += si[t + o]; }
        __syncthreads();
    }
    __shared__ float s_tgtm;
    if (t == 0) {
        float times = (float)(si[0] > 1 ? si[0] : 1);
        float neg_mean = sf[0] / times;
        s_tgtm = (tgt - MARGINF) - (1.f + tgt) * neg_mean;
    }
    __syncthreads();
    const float tgtm = s_tgtm;

    // online softmax over logits = 64 * (j==lab ? tgtm : cos)
    float m = -1e30f, sum = 0.f;
    for (int q = t; q < C_ / 4; q += 512) {
        float4 v = rp[q];
#pragma unroll
        for (int e = 0; e < 4; e++) {
            float c = (&v.x)[e];
            int j = q * 4 + e;
            float z = ((j == lab) ? tgtm : c) * SCALEF;
            if (z > m) {
                sum = sum * expf(m - z) + 1.f;
                m = z;
            } else {
                sum += expf(z - m);
            }
        }
    }
    __shared__ float sm[512];
    __shared__ float ss[512];
    sm[t] = m; ss[t] = sum;
    __syncthreads();
    for (int o = 256; o > 0; o >>= 1) {
        if (t < o) {
            float m2 = sm[t + o], s2 = ss[t + o];
            float M = fmaxf(sm[t], m2);
            ss[t] = ss[t] * expf(sm[t] - M) + s2 * expf(m2 - M);
            sm[t] = M;
        }
        __syncthreads();
    }
    if (t == 0) {
        float lse = sm[0] + logf(ss[0]);
        atomicAdd(&g_loss_sum, lse - tgtm * SCALEF);
    }
}

// ---------------- finalize ----------------
__global__ void k_final(float* out, int out_size) {
    if (threadIdx.x == 0) {
        out[0] = g_loss_sum / 256.0f;
        if (out_size > 1) out[1] = (float)g_acc_sum / 256.0f;
    }
}

// ---------------- launch ----------------
extern "C" void kernel_launch(void* const* d_in, const int* in_sizes, int n_in,
                              void* d_out, int out_size) {
    const float* emb = nullptr;
    const int* lab = nullptr;
    const float* ker = nullptr;
    for (int i = 0; i < n_in; i++) {
        if (in_sizes[i] == B_ * D_) emb = (const float*)d_in[i];
        else if (in_sizes[i] == B_) lab = (const int*)d_in[i];
        else if (in_sizes[i] == D_ * C_) ker = (const float*)d_in[i];
    }

    k_init<<<1, 512>>>();
    k_normA<<<B_, 256>>>(emb);
    k_colnorm<<<(C_ + 255) / 256, 256>>>(ker);
    dim3 gg((C_ + BN - 1) / BN, B_ / BM);
    k_gemm<<<gg, 256>>>(ker);
    k_tgt<<<1, B_>>>(lab);
    k_stats<<<B_, 512>>>(lab);
    k_scan<<<1, 512>>>(1);
    k_hist2<<<B_, 512>>>(lab);
    k_scan<<<1, 512>>>(2);
    k_hist3<<<B_, 512>>>(lab);
    k_scan<<<1, 512>>>(3);
    k_row<<<B_, 512>>>(lab);
    k_final<<<1, 32>>>((float*)d_out, out_size);
}